// round 17
// baseline (speedup 1.0000x reference)
#include <cuda_runtime.h>
#include <cuda_fp16.h>
#include <cstdint>
#include <cstddef>

// Problem constants (fixed by the dataset)
#define NN 100000
#define EE 1600000
#define HH 128
#define CCOUT 40
#define SB 98            // ceil(NN/1024) scan blocks
#define NBLK_GEMM 782    // ceil(NN/128)
#define NBLK_HIST 6250   // EE/256
#define NBLK_FILL 6250   // EE/256

// ---------------- scratch (device globals; no allocation allowed) ----------
// Shadow ping-pong: layer i reads g_hh[i&1], writes g_hh[(i+1)&1]. The fp32
// aggregate lives only in smem inside the fused kernel. Per-layer live set:
// 2 x 25MB shadow + 6.4MB csr ~ 56MB << 126MB L2.
__device__ float g_agg[(size_t)NN * HH];   // final-layer pre-BN output (k_out input)
__device__ __half g_hh0[(size_t)NN * HH];  // fp16 shadow, even layers' source
__device__ __half g_hh1[(size_t)NN * HH];  // fp16 shadow, odd layers' source
__device__ int   g_deg[NN];
__device__ int   g_rowptr[NN + 1];
__device__ int   g_cursor[NN];
__device__ int   g_csr[EE];
__device__ int   g_bsum[SB];
__device__ int   g_boff[SB];
__device__ double g_bnsum[2 * HH];
__device__ float g_scale[HH];
__device__ float g_shift[HH];

// ---------------- fp16 helpers ---------------------------------------------
__device__ __forceinline__ float4 ld_h4(const __half* p) {
    uint2 u = *(const uint2*)p;
    __half2 a = *reinterpret_cast<const __half2*>(&u.x);
    __half2 b = *reinterpret_cast<const __half2*>(&u.y);
    float2 fa = __half22float2(a), fb = __half22float2(b);
    return make_float4(fa.x, fa.y, fb.x, fb.y);
}

// ---------------- CSR build ------------------------------------------------
// zero g_deg; block 0 also zeroes g_bnsum (for the input-layer GEMM stats)
__global__ void k_zero0() {
    int i = blockIdx.x * blockDim.x + threadIdx.x;
    if (i < NN) g_deg[i] = 0;
    if (blockIdx.x == 0) g_bnsum[threadIdx.x] = 0.0;   // 256 threads = 2*HH
}

__global__ void k_bsum() {
    __shared__ int red[256];
    int b = blockIdx.x, t = threadIdx.x;
    int s = 0;
#pragma unroll
    for (int it = 0; it < 4; it++) {
        int idx = b * 1024 + it * 256 + t;
        if (idx < NN) s += g_deg[idx];
    }
    red[t] = s;
    __syncthreads();
    for (int off = 128; off > 0; off >>= 1) {
        if (t < off) red[t] += red[t + off];
        __syncthreads();
    }
    if (t == 0) g_bsum[b] = red[0];
}

// parallel scan of the 98 block sums
__global__ void k_bscan() {
    __shared__ int s[128];
    int t = threadIdx.x;
    int v = (t < SB) ? g_bsum[t] : 0;
    s[t] = v;
    __syncthreads();
    for (int off = 1; off < 128; off <<= 1) {
        int tv = (t >= off) ? s[t - off] : 0;
        __syncthreads();
        s[t] += tv;
        __syncthreads();
    }
    if (t < SB) g_boff[t] = s[t] - v;   // exclusive
    if (t == 0) g_rowptr[NN] = EE;
}

__global__ void k_scan() {
    __shared__ int s[1024];
    int t = threadIdx.x;
    int idx = blockIdx.x * 1024 + t;
    int v = (idx < NN) ? g_deg[idx] : 0;
    s[t] = v;
    __syncthreads();
    for (int off = 1; off < 1024; off <<= 1) {
        int tv = (t >= off) ? s[t - off] : 0;
        __syncthreads();
        s[t] += tv;
        __syncthreads();
    }
    if (idx < NN) {
        int ex = g_boff[blockIdx.x] + s[t] - v;   // exclusive scan + block offset
        g_rowptr[idx] = ex;
        g_cursor[idx] = ex;
    }
}

// fill CSR; the extra last block runs the input-layer BN finalize instead
// (and zeroes g_bnsum for the first fused SAGE GEMM's stats).
__global__ void k_fill_fin(const int* __restrict__ src, const int* __restrict__ dst,
                           const float* __restrict__ g, const float* __restrict__ b) {
    if (blockIdx.x == NBLK_FILL) {
        int c = threadIdx.x;   // 256 threads
        double m = 0.0, var = 0.0;
        if (c < HH) {
            m = g_bnsum[c] / (double)NN;
            var = g_bnsum[HH + c] / (double)NN - m * m;
        }
        __syncthreads();
        g_bnsum[c] = 0.0;      // reset for the next GEMM's fused stats
        if (c < HH) {
            float sc = g[c] * rsqrtf((float)var + 1e-5f);
            g_scale[c] = sc;
            g_shift[c] = b[c] - (float)m * sc;
        }
        return;
    }
    int e = blockIdx.x * blockDim.x + threadIdx.x;
    if (e < EE) {
        int p = atomicAdd(&g_cursor[dst[e]], 1);
        g_csr[p] = src[e];
    }
}

// ---------------- packed f32x2 helpers --------------------------------------
__device__ __forceinline__ unsigned long long pk1(float v) {
    unsigned long long r;
    asm("mov.b64 %0, {%1, %1};" : "=l"(r) : "f"(v));
    return r;
}
__device__ __forceinline__ unsigned long long pk2(float x, float y) {
    unsigned long long r;
    asm("mov.b64 %0, {%1, %2};" : "=l"(r) : "f"(x), "f"(y));
    return r;
}

#define BKG 16

// ---------------- input-layer GEMM (fp32 x, 8 tiles) ------------------------
// C = x @ W_in + b_in; handoff via fp16 shadow g_hh0 + fused BN stats.
// Extra blocks (>= NBLK_GEMM) run the edge histogram (overlaps CSR build).
__global__ __launch_bounds__(256, 2) void k_gemm_in(const float* __restrict__ Aext,
                                                    const float* __restrict__ W1,
                                                    const float* __restrict__ bias,
                                                    const int* __restrict__ dst_h) {
    if (blockIdx.x >= NBLK_GEMM) {
        int e = (blockIdx.x - NBLK_GEMM) * 256 + threadIdx.x;
        if (e < EE) atomicAdd(&g_deg[dst_h[e]], 1);
        return;
    }
    __shared__ unsigned long long As[BKG][130];
    __shared__ float Ws[BKG][HH];
    int tid = threadIdx.x;
    int tx = tid & 15, ty = tid >> 4;
    int r0 = blockIdx.x * 128;
    unsigned long long acc[32];
#pragma unroll
    for (int i = 0; i < 32; i++) acc[i] = 0ULL;

    float4 va[2], vw[2];
    // prologue: tile 0
#pragma unroll
    for (int it = 0; it < 2; it++) {
        int f4i = tid + it * 256;
        int row = f4i >> 2, c4 = f4i & 3;
        va[it] = make_float4(0.f, 0.f, 0.f, 0.f);
        if (r0 + row < NN)
            va[it] = *(const float4*)(Aext + (size_t)(r0 + row) * HH + c4 * 4);
        int k = f4i >> 5, cw = f4i & 31;
        vw[it] = *(const float4*)(W1 + (size_t)k * HH + cw * 4);
    }

    for (int t = 0; t < 8; t++) {
        // store tile t
#pragma unroll
        for (int it = 0; it < 2; it++) {
            int f4i = tid + it * 256;
            int row = f4i >> 2, c4 = f4i & 3;
            float4 v = va[it];
            int k = c4 * 4;
            As[k + 0][row] = pk1(v.x);
            As[k + 1][row] = pk1(v.y);
            As[k + 2][row] = pk1(v.z);
            As[k + 3][row] = pk1(v.w);
            int kw = f4i >> 5, cw = f4i & 31;
            *(float4*)&Ws[kw][cw * 4] = vw[it];
        }
        __syncthreads();
        // prefetch tile t+1
        if (t + 1 < 8) {
            int kbn = (t + 1) * 16;
#pragma unroll
            for (int it = 0; it < 2; it++) {
                int f4i = tid + it * 256;
                int row = f4i >> 2, c4 = f4i & 3;
                va[it] = make_float4(0.f, 0.f, 0.f, 0.f);
                if (r0 + row < NN)
                    va[it] = *(const float4*)(Aext + (size_t)(r0 + row) * HH + kbn + c4 * 4);
                int k = f4i >> 5, cw = f4i & 31;
                vw[it] = *(const float4*)(W1 + (size_t)(kbn + k) * HH + cw * 4);
            }
        }
        // compute
#pragma unroll
        for (int k = 0; k < BKG; k++) {
            ulonglong2 a01 = *(const ulonglong2*)&As[k][ty * 8 + 0];
            ulonglong2 a23 = *(const ulonglong2*)&As[k][ty * 8 + 2];
            ulonglong2 a45 = *(const ulonglong2*)&As[k][ty * 8 + 4];
            ulonglong2 a67 = *(const ulonglong2*)&As[k][ty * 8 + 6];
            ulonglong2 bp01 = *(const ulonglong2*)&Ws[k][tx * 8];
            ulonglong2 bp23 = *(const ulonglong2*)&Ws[k][tx * 8 + 4];
            unsigned long long a[8] = {a01.x, a01.y, a23.x, a23.y,
                                       a45.x, a45.y, a67.x, a67.y};
#pragma unroll
            for (int i = 0; i < 8; i++) {
                asm("fma.rn.f32x2 %0, %1, %2, %0;" : "+l"(acc[i * 4 + 0]) : "l"(a[i]), "l"(bp01.x));
                asm("fma.rn.f32x2 %0, %1, %2, %0;" : "+l"(acc[i * 4 + 1]) : "l"(a[i]), "l"(bp01.y));
                asm("fma.rn.f32x2 %0, %1, %2, %0;" : "+l"(acc[i * 4 + 2]) : "l"(a[i]), "l"(bp23.x));
                asm("fma.rn.f32x2 %0, %1, %2, %0;" : "+l"(acc[i * 4 + 3]) : "l"(a[i]), "l"(bp23.y));
            }
        }
        __syncthreads();
    }

    // epilogue: fp16 shadow + BN stats
    float bcol[8];
#pragma unroll
    for (int j = 0; j < 8; j++) bcol[j] = bias[tx * 8 + j];
    float csum[8], csq[8];
#pragma unroll
    for (int j = 0; j < 8; j++) { csum[j] = 0.f; csq[j] = 0.f; }
#pragma unroll
    for (int i = 0; i < 8; i++) {
        int r = r0 + ty * 8 + i;
        float o[8];
#pragma unroll
        for (int j = 0; j < 4; j++)
            asm("mov.b64 {%0, %1}, %2;" : "=f"(o[2 * j]), "=f"(o[2 * j + 1]) : "l"(acc[i * 4 + j]));
#pragma unroll
        for (int j = 0; j < 8; j++) o[j] += bcol[j];
        if (r < NN) {
            uint4 hv;
            unsigned int* hp = (unsigned int*)&hv;
#pragma unroll
            for (int j = 0; j < 4; j++) {
                unsigned short lo = __half_as_ushort(__float2half_rn(o[2 * j]));
                unsigned short hi = __half_as_ushort(__float2half_rn(o[2 * j + 1]));
                hp[j] = ((unsigned int)hi << 16) | lo;
            }
            *(uint4*)(g_hh0 + (size_t)r * HH + tx * 8) = hv;
#pragma unroll
            for (int j = 0; j < 8; j++) { csum[j] += o[j]; csq[j] += o[j] * o[j]; }
        }
    }
    float* red = (float*)As;
#pragma unroll
    for (int j = 0; j < 8; j++) {
        red[ty * 256 + tx * 8 + j] = csum[j];
        red[ty * 256 + 128 + tx * 8 + j] = csq[j];
    }
    __syncthreads();
    if (tid < HH) {
        float s = 0.f, q = 0.f;
#pragma unroll
        for (int t = 0; t < 16; t++) {
            s += red[t * 256 + tid];
            q += red[t * 256 + 128 + tid];
        }
        atomicAdd(&g_bnsum[tid], (double)s);
        atomicAdd(&g_bnsum[HH + tid], (double)q);
    }
}

// ---------------- fused SAGE layer: aggregate (smem) + dual GEMM -----------
// Phase A: each CTA aggregates its 128 rows (BN+ReLU'd fp16 shadow gather,
//          warp-per-node) into a padded fp32 smem tile.
// Phase B: C = agg @ W1 + relu(bn(shadow)) @ W2 + bias. Phase-0 A comes
//          straight from smem; phase-1 prefetches the shadow from gmem.
// stats==1: handoff via fp16 shadow (ping-pong) + BN column stats.
// stats==0: final layer -- write fp32 g_agg for k_out.
#define AGG_STRIDE 132
#define AGG_BYTES (128 * AGG_STRIDE * 4)

__global__ __launch_bounds__(256, 2) void k_gemm_fused(const float* __restrict__ W1,
                                                       const float* __restrict__ W2,
                                                       const float* __restrict__ bias,
                                                       int stats, int par) {
    extern __shared__ float s_agg[];   // [128][AGG_STRIDE]
    __shared__ unsigned long long As[BKG][130];
    __shared__ float Ws[BKG][HH];
    __shared__ float sc_s[HH], sf_s[HH];
    const __half* shadow = par ? g_hh1 : g_hh0;
    __half* sdst = par ? g_hh0 : g_hh1;
    int tid = threadIdx.x;
    int tx = tid & 15, ty = tid >> 4;
    int wid = tid >> 5, lane = tid & 31;
    int r0 = blockIdx.x * 128;

    if (tid < HH) { sc_s[tid] = g_scale[tid]; sf_s[tid] = g_shift[tid]; }
    __syncthreads();

    // ---- Phase A: aggregate this CTA's 128 rows into smem ----
    {
        int cb = lane * 4;
        float4 sc = *(const float4*)&sc_s[cb];
        float4 sf = *(const float4*)&sf_s[cb];
        for (int i = 0; i < 16; i++) {
            int lrow = wid * 16 + i;
            int node = r0 + lrow;
            if (node >= NN) break;
            int s0 = g_rowptr[node], s1 = g_rowptr[node + 1];
            float4 a4 = make_float4(0.f, 0.f, 0.f, 0.f);
            int j = s0;
            for (; j + 4 <= s1; j += 4) {
                int a = g_csr[j], b = g_csr[j + 1], c = g_csr[j + 2], d = g_csr[j + 3];
                float4 va = ld_h4(shadow + (size_t)a * HH + cb);
                float4 vb = ld_h4(shadow + (size_t)b * HH + cb);
                float4 vc = ld_h4(shadow + (size_t)c * HH + cb);
                float4 vd = ld_h4(shadow + (size_t)d * HH + cb);
                a4.x += fmaxf(va.x * sc.x + sf.x, 0.f) + fmaxf(vb.x * sc.x + sf.x, 0.f)
                      + fmaxf(vc.x * sc.x + sf.x, 0.f) + fmaxf(vd.x * sc.x + sf.x, 0.f);
                a4.y += fmaxf(va.y * sc.y + sf.y, 0.f) + fmaxf(vb.y * sc.y + sf.y, 0.f)
                      + fmaxf(vc.y * sc.y + sf.y, 0.f) + fmaxf(vd.y * sc.y + sf.y, 0.f);
                a4.z += fmaxf(va.z * sc.z + sf.z, 0.f) + fmaxf(vb.z * sc.z + sf.z, 0.f)
                      + fmaxf(vc.z * sc.z + sf.z, 0.f) + fmaxf(vd.z * sc.z + sf.z, 0.f);
                a4.w += fmaxf(va.w * sc.w + sf.w, 0.f) + fmaxf(vb.w * sc.w + sf.w, 0.f)
                      + fmaxf(vc.w * sc.w + sf.w, 0.f) + fmaxf(vd.w * sc.w + sf.w, 0.f);
            }
            for (; j < s1; j++) {
                int a = g_csr[j];
                float4 va = ld_h4(shadow + (size_t)a * HH + cb);
                a4.x += fmaxf(va.x * sc.x + sf.x, 0.f);
                a4.y += fmaxf(va.y * sc.y + sf.y, 0.f);
                a4.z += fmaxf(va.z * sc.z + sf.z, 0.f);
                a4.w += fmaxf(va.w * sc.w + sf.w, 0.f);
            }
            float inv = (s1 > s0) ? 1.0f / (float)(s1 - s0) : 0.0f;
            a4.x *= inv; a4.y *= inv; a4.z *= inv; a4.w *= inv;
            *(float4*)&s_agg[(size_t)lrow * AGG_STRIDE + cb] = a4;
        }
    }
    __syncthreads();

    // ---- Phase B: dual GEMM ----
    unsigned long long acc[32];
#pragma unroll
    for (int i = 0; i < 32; i++) acc[i] = 0ULL;
    float4 va[2], vw[2];
    // prologue: tile 0 weights (A comes from smem at store time)
#pragma unroll
    for (int it = 0; it < 2; it++) {
        int f4i = tid + it * 256;
        int k = f4i >> 5, cw = f4i & 31;
        vw[it] = *(const float4*)(W1 + (size_t)k * HH + cw * 4);
    }

    for (int t = 0; t < 16; t++) {
        int kb = (t & 7) * 16;
        int p1 = (t >= 8);
        // store tile t
#pragma unroll
        for (int it = 0; it < 2; it++) {
            int f4i = tid + it * 256;
            int row = f4i >> 2, c4 = f4i & 3;
            float4 v;
            if (!p1) {
                v = *(const float4*)&s_agg[(size_t)row * AGG_STRIDE + kb + c4 * 4];
            } else {
                v = va[it];
                float4 scv = *(const float4*)&sc_s[kb + c4 * 4];
                float4 sfv = *(const float4*)&sf_s[kb + c4 * 4];
                v.x = fmaxf(v.x * scv.x + sfv.x, 0.f);
                v.y = fmaxf(v.y * scv.y + sfv.y, 0.f);
                v.z = fmaxf(v.z * scv.z + sfv.z, 0.f);
                v.w = fmaxf(v.w * scv.w + sfv.w, 0.f);
            }
            int k = c4 * 4;
            As[k + 0][row] = pk1(v.x);
            As[k + 1][row] = pk1(v.y);
            As[k + 2][row] = pk1(v.z);
            As[k + 3][row] = pk1(v.w);
            int kw = f4i >> 5, cw = f4i & 31;
            *(float4*)&Ws[kw][cw * 4] = vw[it];
        }
        __syncthreads();
        // prefetch tile t+1 (A only for phase-1 tiles; W always)
        if (t + 1 < 16) {
            int tn = t + 1;
            int kbn = (tn & 7) * 16;
            const float* Wp = (tn >= 8) ? W2 : W1;
            if (tn >= 8) {
#pragma unroll
                for (int it = 0; it < 2; it++) {
                    int f4i = tid + it * 256;
                    int row = f4i >> 2, c4 = f4i & 3;
                    va[it] = make_float4(0.f, 0.f, 0.f, 0.f);
                    if (r0 + row < NN)
                        va[it] = ld_h4(shadow + (size_t)(r0 + row) * HH + kbn + c4 * 4);
                }
            }
#pragma unroll
            for (int it = 0; it < 2; it++) {
                int f4i = tid + it * 256;
                int k = f4i >> 5, cw = f4i & 31;
                vw[it] = *(const float4*)(Wp + (size_t)(kbn + k) * HH + cw * 4);
            }
        }
        // compute tile t
#pragma unroll
        for (int k = 0; k < BKG; k++) {
            ulonglong2 a01 = *(const ulonglong2*)&As[k][ty * 8 + 0];
            ulonglong2 a23 = *(const ulonglong2*)&As[k][ty * 8 + 2];
            ulonglong2 a45 = *(const ulonglong2*)&As[k][ty * 8 + 4];
            ulonglong2 a67 = *(const ulonglong2*)&As[k][ty * 8 + 6];
            ulonglong2 bp01 = *(const ulonglong2*)&Ws[k][tx * 8];
            ulonglong2 bp23 = *(const ulonglong2*)&Ws[k][tx * 8 + 4];
            unsigned long long a[8] = {a01.x, a01.y, a23.x, a23.y,
                                       a45.x, a45.y, a67.x, a67.y};
#pragma unroll
            for (int i = 0; i < 8; i++) {
                asm("fma.rn.f32x2 %0, %1, %2, %0;" : "+l"(acc[i * 4 + 0]) : "l"(a[i]), "l"(bp01.x));
                asm("fma.rn.f32x2 %0, %1, %2, %0;" : "+l"(acc[i * 4 + 1]) : "l"(a[i]), "l"(bp01.y));
                asm("fma.rn.f32x2 %0, %1, %2, %0;" : "+l"(acc[i * 4 + 2]) : "l"(a[i]), "l"(bp23.x));
                asm("fma.rn.f32x2 %0, %1, %2, %0;" : "+l"(acc[i * 4 + 3]) : "l"(a[i]), "l"(bp23.y));
            }
        }
        __syncthreads();
    }

    // ---- epilogue ----
    float bcol[8];
#pragma unroll
    for (int j = 0; j < 8; j++) bcol[j] = bias[tx * 8 + j];
    float csum[8], csq[8];
#pragma unroll
    for (int j = 0; j < 8; j++) { csum[j] = 0.f; csq[j] = 0.f; }
#pragma unroll
    for (int i = 0; i < 8; i++) {
        int r = r0 + ty * 8 + i;
        float o[8];
#pragma unroll
        for (int j = 0; j < 4; j++)
            asm("mov.b64 {%0, %1}, %2;" : "=f"(o[2 * j]), "=f"(o[2 * j + 1]) : "l"(acc[i * 4 + j]));
#pragma unroll
        for (int j = 0; j < 8; j++) o[j] += bcol[j];
        if (r < NN) {
            if (stats) {
                uint4 hv;
                unsigned int* hp = (unsigned int*)&hv;
#pragma unroll
                for (int j = 0; j < 4; j++) {
                    unsigned short lo = __half_as_ushort(__float2half_rn(o[2 * j]));
                    unsigned short hi = __half_as_ushort(__float2half_rn(o[2 * j + 1]));
                    hp[j] = ((unsigned int)hi << 16) | lo;
                }
                *(uint4*)(sdst + (size_t)r * HH + tx * 8) = hv;
#pragma unroll
                for (int j = 0; j < 8; j++) { csum[j] += o[j]; csq[j] += o[j] * o[j]; }
            } else {
                float4 v0 = make_float4(o[0], o[1], o[2], o[3]);
                float4 v1 = make_float4(o[4], o[5], o[6], o[7]);
                *(float4*)(g_agg + (size_t)r * HH + tx * 8) = v0;
                *(float4*)(g_agg + (size_t)r * HH + tx * 8 + 4) = v1;
            }
        }
    }
    if (stats) {
        float* red = (float*)As;
#pragma unroll
        for (int j = 0; j < 8; j++) {
            red[ty * 256 + tx * 8 + j] = csum[j];
            red[ty * 256 + 128 + tx * 8 + j] = csq[j];
        }
        __syncthreads();
        if (tid < HH) {
            float s = 0.f, q = 0.f;
#pragma unroll
            for (int t = 0; t < 16; t++) {
                s += red[t * 256 + tid];
                q += red[t * 256 + 128 + tid];
            }
            atomicAdd(&g_bnsum[tid], (double)s);
            atomicAdd(&g_bnsum[HH + tid], (double)q);
        }
    }
}

// ---------------- BN finalize (zeroes accumulators after reading) ----------
__global__ void k_finalize(const float* __restrict__ g, const float* __restrict__ b) {
    int c = threadIdx.x;   // 256 threads
    double m = 0.0, var = 0.0;
    if (c < HH) {
        m = g_bnsum[c] / (double)NN;
        var = g_bnsum[HH + c] / (double)NN - m * m;
    }
    __syncthreads();
    g_bnsum[c] = 0.0;
    if (c < HH) {
        float sc = g[c] * rsqrtf((float)var + 1e-5f);
        g_scale[c] = sc;
        g_shift[c] = b[c] - (float)m * sc;
    }
}

// ---------------- final projection (N x 128) @ (128 x 40), f32x2 -----------
__global__ __launch_bounds__(256) void k_out(const float* __restrict__ Wo,
                                             const float* __restrict__ bo,
                                             float* __restrict__ out) {
    __shared__ unsigned long long Wsd[HH * 20];   // [k][20 col-pairs]
    __shared__ unsigned long long As[16 * 128];   // [k][row] dup pairs
    int tid = threadIdx.x;
    int tx = tid & 3, ty = tid >> 2;
    int r0 = blockIdx.x * 128;
    for (int i = tid; i < HH * 20; i += 256) {
        int k = i / 20, p = i % 20;
        Wsd[i] = pk2(Wo[k * CCOUT + p * 2], Wo[k * CCOUT + p * 2 + 1]);
    }
    unsigned long long acc[2][5];
#pragma unroll
    for (int r = 0; r < 2; r++)
#pragma unroll
        for (int p = 0; p < 5; p++) acc[r][p] = 0ULL;

    for (int kb = 0; kb < HH; kb += 16) {
        __syncthreads();
#pragma unroll
        for (int it = 0; it < 2; it++) {
            int f4i = tid + it * 256;
            int row = f4i >> 2, c4 = f4i & 3;
            float4 v = make_float4(0.f, 0.f, 0.f, 0.f);
            if (r0 + row < NN)
                v = *(const float4*)(g_agg + (size_t)(r0 + row) * HH + kb + c4 * 4);
            As[(c4 * 4 + 0) * 128 + row] = pk1(v.x);
            As[(c4 * 4 + 1) * 128 + row] = pk1(v.y);
            As[(c4 * 4 + 2) * 128 + row] = pk1(v.z);
            As[(c4 * 4 + 3) * 128 + row] = pk1(v.w);
        }
        __syncthreads();
#pragma unroll
        for (int k = 0; k < 16; k++) {
            ulonglong2 a = *(const ulonglong2*)&As[k * 128 + ty * 2];
            const unsigned long long* brow = &Wsd[(kb + k) * 20 + tx * 5];
#pragma unroll
            for (int p = 0; p < 5; p++) {
                unsigned long long b = brow[p];
                asm("fma.rn.f32x2 %0, %1, %2, %0;" : "+l"(acc[0][p]) : "l"(a.x), "l"(b));
                asm("fma.rn.f32x2 %0, %1, %2, %0;" : "+l"(acc[1][p]) : "l"(a.y), "l"(b));
            }
        }
    }
#pragma unroll
    for (int r = 0; r < 2; r++) {
        int row = r0 + ty * 2 + r;
        if (row < NN) {
#pragma unroll
            for (int p = 0; p < 5; p++) {
                float lo, hi;
                asm("mov.b64 {%0, %1}, %2;" : "=f"(lo), "=f"(hi) : "l"(acc[r][p]));
                int c = tx * 10 + p * 2;
                float2 v = make_float2(lo + bo[c], hi + bo[c + 1]);
                *(float2*)(out + (size_t)row * CCOUT + c) = v;
            }
        }
    }
}

// ---------------- driver ---------------------------------------------------
extern "C" void kernel_launch(void* const* d_in, const int* in_sizes, int n_in,
                              void* d_out, int out_size) {
    const float* x       = (const float*)d_in[0];
    const float* W_in    = (const float*)d_in[1];
    const float* b_in    = (const float*)d_in[2];
    const float* g_in    = (const float*)d_in[3];
    const float* beta_in = (const float*)d_in[4];
    const float* Wl      = (const float*)d_in[5];
    const float* bl      = (const float*)d_in[6];
    const float* Wr      = (const float*)d_in[7];
    const float* gbn     = (const float*)d_in[8];
    const float* bbn     = (const float*)d_in[9];
    const float* W_out   = (const float*)d_in[10];
    const float* b_out   = (const float*)d_in[11];
    const int*   ei      = (const int*)d_in[12];
    const int* src = ei;
    const int* dst = ei + EE;
    float* out = (float*)d_out;

    cudaFuncSetAttribute(k_gemm_fused, cudaFuncAttributeMaxDynamicSharedMemorySize,
                         AGG_BYTES);

    // zero degree histogram + input-layer BN accumulators
    k_zero0<<<(NN + 255) / 256, 256>>>();

    // Input-layer GEMM (fp16 shadow g_hh0 + fused stats) with edge histogram
    // riding on the same grid's extra blocks.
    k_gemm_in<<<NBLK_GEMM + NBLK_HIST, 256>>>(x, W_in, b_in, dst);

    // CSR prefix-sum chain; fill kernel's extra block finalizes input BN
    // and zeroes the stat accumulators for the first fused layer.
    k_bsum<<<SB, 256>>>();
    k_bscan<<<1, 128>>>();
    k_scan<<<SB, 1024>>>();
    k_fill_fin<<<NBLK_FILL + 1, 256>>>(src, dst, g_in, beta_in);

    // Fused SAGE layers: aggregate (smem) + dual GEMM, shadow ping-pong.
    for (int i = 0; i < 4; i++) {
        k_gemm_fused<<<NBLK_GEMM, 256, AGG_BYTES>>>(Wl + (size_t)i * HH * HH,
                                                    Wr + (size_t)i * HH * HH,
                                                    bl + (size_t)i * HH,
                                                    (i < 3) ? 1 : 0, i & 1);
        if (i < 3) k_finalize<<<1, 256>>>(gbn + i * HH, bbn + i * HH);
    }

    // Output projection from the raw (no BN) last-layer activations in g_agg
    k_out<<<NBLK_GEMM, 256>>>(W_out, b_out, out);
}